// round 1
// baseline (speedup 1.0000x reference)
#include <cuda_runtime.h>
#include <cuda_bf16.h>
#include <math_constants.h>

// Problem constants (hardcoded in reference)
#define BB 4
#define LL 8192
#define DD 768
#define MAXS 100

#define GM (BB*MAXS)   // 400
#define GN DD          // 768
#define GK DD          // 768

// GEMM tiling
#define BM 100
#define BN 64
#define KC 16
#define SPLITK 3
#define KCHUNK (GK/SPLITK)  // 256
#define GEMM_THREADS 320

// Scratch (device globals: no allocation allowed)
__device__ float g_pooled[GM * GK];                 // [400][768] pooled sentence features
__device__ float g_part[SPLITK][GM * GN];           // split-K partial sums

// ---------------------------------------------------------------------------
// Kernel 1: segment-max pooling.
// ids[b, :] is sorted ascending, values in [0, 99]. Tokens with id v = s+1
// form contiguous span -> binary search. bb = ids[b, L-1] (max since sorted).
// pooled[b, s, :] = max over span, 0 if s >= bb, -inf if span empty (matches
// jax segment_max identity; practically never happens).
// Grid: (100, 4), 256 threads. Each thread owns 3 columns (d, d+256, d+512).
// ---------------------------------------------------------------------------
__global__ __launch_bounds__(256) void pool_kernel(const float* __restrict__ wf,
                                                   const int* __restrict__ ids) {
    const int s = blockIdx.x;          // sentence slot 0..99
    const int b = blockIdx.y;          // batch row
    const int tid = threadIdx.x;       // 0..255
    const int* __restrict__ row = ids + (size_t)b * LL;
    float* __restrict__ outp = g_pooled + ((size_t)b * MAXS + s) * DD;

    const int bbmax = row[LL - 1];
    if (s >= bbmax) {
        outp[tid]       = 0.0f;
        outp[tid + 256] = 0.0f;
        outp[tid + 512] = 0.0f;
        return;
    }

    const int v = s + 1;
    // lower_bound(v)
    int lo = 0, hi = LL;
    while (lo < hi) { int m = (lo + hi) >> 1; if (row[m] < v) lo = m + 1; else hi = m; }
    const int start = lo;
    // lower_bound(v+1)
    hi = LL;
    while (lo < hi) { int m = (lo + hi) >> 1; if (row[m] < v + 1) lo = m + 1; else hi = m; }
    const int end = lo;

    float m0 = -CUDART_INF_F, m1 = -CUDART_INF_F, m2 = -CUDART_INF_F;
    const float* __restrict__ base = wf + (size_t)b * LL * DD;

    int t = start;
    // unroll-by-2 over tokens: 6 independent LDGs in flight per thread
    for (; t + 1 < end; t += 2) {
        const float* r0 = base + (size_t)t * DD;
        const float* r1 = r0 + DD;
        float a0 = r0[tid], a1 = r0[tid + 256], a2 = r0[tid + 512];
        float c0 = r1[tid], c1 = r1[tid + 256], c2 = r1[tid + 512];
        m0 = fmaxf(m0, fmaxf(a0, c0));
        m1 = fmaxf(m1, fmaxf(a1, c1));
        m2 = fmaxf(m2, fmaxf(a2, c2));
    }
    if (t < end) {
        const float* r0 = base + (size_t)t * DD;
        m0 = fmaxf(m0, r0[tid]);
        m1 = fmaxf(m1, r0[tid + 256]);
        m2 = fmaxf(m2, r0[tid + 512]);
    }

    outp[tid]       = m0;
    outp[tid + 256] = m1;
    outp[tid + 512] = m2;
}

// ---------------------------------------------------------------------------
// Kernel 2: split-K fp32 GEMM.  part[z][m][n] = sum_{k in chunk z} A[m][k]*W2[n][k]
// A = g_pooled [400][768] row-major (k contiguous), W2 [768][768] row-major
// (k contiguous) -> both loads are along contiguous k. 320 threads:
// tx = tid%16 covers n in micro-tiles of 4 (16*4=64), ty = tid/16 in [0,20)
// covers m in micro-tiles of 5 (20*5=100). Grid (4, 12, 3) = 144 blocks ->
// exactly one wave, one block per SM, each ~25.6k FMA-bound cycles.
// ---------------------------------------------------------------------------
__global__ __launch_bounds__(GEMM_THREADS) void gemm_kernel(const float* __restrict__ W2) {
    __shared__ float As[KC][BM + 4];   // [k][m], padded
    __shared__ float Bs[KC][BN + 4];   // [k][n], padded

    const int mb = blockIdx.x * BM;        // 0,100,200,300
    const int nb = blockIdx.y * BN;        // 0..704
    const int kz = blockIdx.z;             // split-K index
    const int k0base = kz * KCHUNK;

    const int tid = threadIdx.x;
    const int tx = tid & 15;               // 0..15  (n)
    const int ty = tid >> 4;               // 0..19  (m)
    const int ty5 = ty * 5;
    const int tx4 = tx * 4;

    float acc[5][4];
#pragma unroll
    for (int i = 0; i < 5; ++i)
#pragma unroll
        for (int j = 0; j < 4; ++j) acc[i][j] = 0.0f;

    for (int kt = 0; kt < KCHUNK; kt += KC) {
        const int k0 = k0base + kt;
        // load A tile: 100x16 = 1600 floats, 320 thr -> exactly 5 each
#pragma unroll
        for (int i = tid; i < BM * KC; i += GEMM_THREADS) {
            int m = i >> 4;            // i / KC
            int k = i & 15;            // i % KC
            As[k][m] = g_pooled[(mb + m) * GK + k0 + k];
        }
        // load B tile: 64x16 = 1024 floats
        for (int i = tid; i < BN * KC; i += GEMM_THREADS) {
            int n = i >> 4;
            int k = i & 15;
            Bs[k][n] = W2[(size_t)(nb + n) * GK + k0 + k];
        }
        __syncthreads();

#pragma unroll
        for (int k = 0; k < KC; ++k) {
            float a[5], bq[4];
#pragma unroll
            for (int i = 0; i < 5; ++i) a[i] = As[k][ty5 + i];
#pragma unroll
            for (int j = 0; j < 4; ++j) bq[j] = Bs[k][tx4 + j];
#pragma unroll
            for (int i = 0; i < 5; ++i)
#pragma unroll
                for (int j = 0; j < 4; ++j)
                    acc[i][j] = fmaf(a[i], bq[j], acc[i][j]);
        }
        __syncthreads();
    }

    float* __restrict__ part = g_part[kz];
#pragma unroll
    for (int i = 0; i < 5; ++i) {
        int m = mb + ty5 + i;
#pragma unroll
        for (int j = 0; j < 4; ++j) {
            part[(size_t)m * GN + nb + tx4 + j] = acc[i][j];
        }
    }
}

// ---------------------------------------------------------------------------
// Kernel 3: combine split-K partials + bias -> output [4,100,768] fp32
// ---------------------------------------------------------------------------
__global__ __launch_bounds__(256) void combine_kernel(const float* __restrict__ b2,
                                                      float* __restrict__ out) {
    int i = blockIdx.x * 256 + threadIdx.x;
    if (i >= GM * GN) return;
    int n = i % GN;
    out[i] = g_part[0][i] + g_part[1][i] + g_part[2][i] + b2[n];
}

// ---------------------------------------------------------------------------
extern "C" void kernel_launch(void* const* d_in, const int* in_sizes, int n_in,
                              void* d_out, int out_size) {
    const float* wf  = (const float*)d_in[0];   // [4,8192,768] f32
    const int*   ids = (const int*)d_in[1];     // [4,64,128] i32 (== [4,8192])
    const float* W2  = (const float*)d_in[2];   // [768,768] f32
    const float* b2  = (const float*)d_in[3];   // [768] f32
    float* out = (float*)d_out;                 // [4,100,768] f32

    pool_kernel<<<dim3(MAXS, BB), 256>>>(wf, ids);
    gemm_kernel<<<dim3(GM / BM, GN / BN, SPLITK), GEMM_THREADS>>>(W2);
    combine_kernel<<<(GM * GN + 255) / 256, 256>>>(b2, out);
}

// round 2
// speedup vs baseline: 1.6043x; 1.6043x over previous
#include <cuda_runtime.h>
#include <math_constants.h>

// Problem constants
#define BB 4
#define LL 8192
#define DD 768
#define MAXS 100
#define GM (BB*MAXS)   // 400
#define GN DD          // 768
#define GK DD          // 768

// pool config
#define TCH 32
#define PBLK 192

// gemm config
#define SPLITK 3
#define KCHUNK (GK/SPLITK)  // 256
#define KC 32
#define BMT 100
#define BNT 32
#define GT 160

// Scratch (device globals; allocation is forbidden)
__device__ float g_pooledT[GK][GM];        // [768][400]  A^T, k-major
__device__ float g_W2T[GK][GN];            // [768][768]  W2^T, k-major
__device__ float g_part[SPLITK][GM * GN];  // split-K partials

// ---------------------------------------------------------------------------
// float atomic max (exact, order-independent -> deterministic)
// ---------------------------------------------------------------------------
__device__ __forceinline__ void atomMaxF(float* a, float v) {
    if (v >= 0.0f) atomicMax((int*)a, __float_as_int(v));
    else           atomicMin((unsigned int*)a, __float_as_uint(v));
}

// ---------------------------------------------------------------------------
// Init pooledT: -inf where sentence slot valid (s < bb[b]), else 0
// ---------------------------------------------------------------------------
__global__ __launch_bounds__(1024) void init_kernel(const int* __restrict__ ids) {
    int i = blockIdx.x * 1024 + threadIdx.x;       // over GK*GM = 307200
    int m = i % GM;
    int b = m / MAXS;
    int s = m - b * MAXS;
    int bbmax = ids[b * LL + LL - 1];              // ids sorted -> max id
    ((float*)g_pooledT)[i] = (s < bbmax) ? -CUDART_INF_F : 0.0f;
}

// ---------------------------------------------------------------------------
// Transpose W2 [n][k] -> g_W2T [k][n]
// ---------------------------------------------------------------------------
__global__ __launch_bounds__(256) void transpose_kernel(const float* __restrict__ W2) {
    __shared__ float tile[32][33];
    int bx = blockIdx.x * 32;   // k base
    int by = blockIdx.y * 32;   // n base
    int x = threadIdx.x, y = threadIdx.y;   // 32 x 8
#pragma unroll
    for (int j = 0; j < 32; j += 8)
        tile[y + j][x] = W2[(size_t)(by + y + j) * GK + bx + x];
    __syncthreads();
#pragma unroll
    for (int j = 0; j < 32; j += 8)
        g_W2T[bx + y + j][by + x] = tile[x][y + j];
}

// ---------------------------------------------------------------------------
// Pool: token-parallel segment max. grid (L/TCH, B), 192 threads.
// Thread owns float4 column d4=tid. ids sorted -> flushes are rare & uniform.
// 8 independent LDG.128 per thread per inner group.
// ---------------------------------------------------------------------------
__global__ __launch_bounds__(PBLK) void pool_kernel(const float* __restrict__ wf,
                                                    const int* __restrict__ ids) {
    __shared__ int sid[TCH];
    const int b = blockIdx.y;
    const int c0 = blockIdx.x * TCH;
    const int tid = threadIdx.x;
    if (tid < TCH) sid[tid] = ids[b * LL + c0 + tid];
    __syncthreads();

    const float4* __restrict__ base =
        (const float4*)(wf + ((size_t)b * LL + c0) * DD) + tid;   // row stride DD/4

    float4 run = make_float4(-CUDART_INF_F, -CUDART_INF_F, -CUDART_INF_F, -CUDART_INF_F);
    int cur = -1;
    const int d0 = tid * 4;

#pragma unroll
    for (int t0 = 0; t0 < TCH; t0 += 8) {
        float4 v[8];
#pragma unroll
        for (int j = 0; j < 8; ++j)
            v[j] = base[(size_t)(t0 + j) * (DD / 4)];
#pragma unroll
        for (int j = 0; j < 8; ++j) {
            int id = sid[t0 + j];
            if (id != cur) {
                if (cur > 0) {
                    int m = b * MAXS + cur - 1;
                    atomMaxF(&g_pooledT[d0 + 0][m], run.x);
                    atomMaxF(&g_pooledT[d0 + 1][m], run.y);
                    atomMaxF(&g_pooledT[d0 + 2][m], run.z);
                    atomMaxF(&g_pooledT[d0 + 3][m], run.w);
                }
                cur = id;
                run = make_float4(-CUDART_INF_F, -CUDART_INF_F, -CUDART_INF_F, -CUDART_INF_F);
            }
            if (id > 0) {
                run.x = fmaxf(run.x, v[j].x);
                run.y = fmaxf(run.y, v[j].y);
                run.z = fmaxf(run.z, v[j].z);
                run.w = fmaxf(run.w, v[j].w);
            }
        }
    }
    if (cur > 0) {
        int m = b * MAXS + cur - 1;
        atomMaxF(&g_pooledT[d0 + 0][m], run.x);
        atomMaxF(&g_pooledT[d0 + 1][m], run.y);
        atomMaxF(&g_pooledT[d0 + 2][m], run.z);
        atomMaxF(&g_pooledT[d0 + 3][m], run.w);
    }
}

// ---------------------------------------------------------------------------
// GEMM: part[kz][m][n] = sum_{k in chunk} AT[k][m] * W2T[k][n]
// grid (4, 24, 3) = 288 blocks (2/SM). 160 threads = 5 warps.
// micro-tile 5x4; register prefetch of next K-tile hides global latency.
// ---------------------------------------------------------------------------
__global__ __launch_bounds__(GT) void gemm_kernel() {
    __shared__ float As[KC][BMT];       // 12.8 KB, stores conflict-free (m contig)
    __shared__ float Bs[KC][BNT + 4];   // 4.6 KB, row 144B -> b LDS.128 aligned

    const int mb = blockIdx.x * BMT;
    const int nb = blockIdx.y * BNT;
    const int kz = blockIdx.z;
    const int k0 = kz * KCHUNK;

    const int tid = threadIdx.x;
    const int tx = tid & 7;     // n micro (x4)
    const int ty = tid >> 3;    // m micro (x5)
    const int ty5 = ty * 5;
    const int tx4 = tx * 4;

    float acc[5][4];
#pragma unroll
    for (int i = 0; i < 5; ++i)
#pragma unroll
        for (int j = 0; j < 4; ++j) acc[i][j] = 0.0f;

    float areg[20];   // 3200/160 = 20
    float breg[7];    // ceil(1024/160) = 7

    // prefetch tile 0
#pragma unroll
    for (int j = 0; j < 20; ++j) {
        int i = tid + j * GT;
        int k = i / BMT, m = i - k * BMT;
        areg[j] = g_pooledT[k0 + k][mb + m];
    }
#pragma unroll
    for (int j = 0; j < 7; ++j) {
        int i = tid + j * GT;
        if (i < KC * BNT) {
            int k = i >> 5, n = i & 31;
            breg[j] = g_W2T[k0 + k][nb + n];
        }
    }

    for (int kt = 0; kt < KCHUNK; kt += KC) {
        // regs -> smem
#pragma unroll
        for (int j = 0; j < 20; ++j) {
            int i = tid + j * GT;
            int k = i / BMT, m = i - k * BMT;
            As[k][m] = areg[j];
        }
#pragma unroll
        for (int j = 0; j < 7; ++j) {
            int i = tid + j * GT;
            if (i < KC * BNT) {
                int k = i >> 5, n = i & 31;
                Bs[k][n] = breg[j];
            }
        }
        __syncthreads();

        // prefetch next tile while computing this one
        if (kt + KC < KCHUNK) {
            int kn = k0 + kt + KC;
#pragma unroll
            for (int j = 0; j < 20; ++j) {
                int i = tid + j * GT;
                int k = i / BMT, m = i - k * BMT;
                areg[j] = g_pooledT[kn + k][mb + m];
            }
#pragma unroll
            for (int j = 0; j < 7; ++j) {
                int i = tid + j * GT;
                if (i < KC * BNT) {
                    int k = i >> 5, n = i & 31;
                    breg[j] = g_W2T[kn + k][nb + n];
                }
            }
        }

#pragma unroll
        for (int k = 0; k < KC; ++k) {
            float a0 = As[k][ty5 + 0];
            float a1 = As[k][ty5 + 1];
            float a2 = As[k][ty5 + 2];
            float a3 = As[k][ty5 + 3];
            float a4 = As[k][ty5 + 4];
            float4 b4 = *(const float4*)&Bs[k][tx4];
            acc[0][0] = fmaf(a0, b4.x, acc[0][0]); acc[0][1] = fmaf(a0, b4.y, acc[0][1]);
            acc[0][2] = fmaf(a0, b4.z, acc[0][2]); acc[0][3] = fmaf(a0, b4.w, acc[0][3]);
            acc[1][0] = fmaf(a1, b4.x, acc[1][0]); acc[1][1] = fmaf(a1, b4.y, acc[1][1]);
            acc[1][2] = fmaf(a1, b4.z, acc[1][2]); acc[1][3] = fmaf(a1, b4.w, acc[1][3]);
            acc[2][0] = fmaf(a2, b4.x, acc[2][0]); acc[2][1] = fmaf(a2, b4.y, acc[2][1]);
            acc[2][2] = fmaf(a2, b4.z, acc[2][2]); acc[2][3] = fmaf(a2, b4.w, acc[2][3]);
            acc[3][0] = fmaf(a3, b4.x, acc[3][0]); acc[3][1] = fmaf(a3, b4.y, acc[3][1]);
            acc[3][2] = fmaf(a3, b4.z, acc[3][2]); acc[3][3] = fmaf(a3, b4.w, acc[3][3]);
            acc[4][0] = fmaf(a4, b4.x, acc[4][0]); acc[4][1] = fmaf(a4, b4.y, acc[4][1]);
            acc[4][2] = fmaf(a4, b4.z, acc[4][2]); acc[4][3] = fmaf(a4, b4.w, acc[4][3]);
        }
        __syncthreads();
    }

    float* __restrict__ part = g_part[kz];
#pragma unroll
    for (int i = 0; i < 5; ++i) {
        int m = mb + ty5 + i;
        float4 st = make_float4(acc[i][0], acc[i][1], acc[i][2], acc[i][3]);
        *(float4*)&part[(size_t)m * GN + nb + tx4] = st;
    }
}

// ---------------------------------------------------------------------------
// Combine split-K partials + bias (vectorized float4)
// ---------------------------------------------------------------------------
__global__ __launch_bounds__(256) void combine_kernel(const float* __restrict__ b2,
                                                      float* __restrict__ out) {
    int i = blockIdx.x * 256 + threadIdx.x;       // over GM*GN/4 = 76800
    const float4* p0 = (const float4*)g_part[0];
    const float4* p1 = (const float4*)g_part[1];
    const float4* p2 = (const float4*)g_part[2];
    const float4* bb4 = (const float4*)b2;
    float4 a = p0[i], b = p1[i], c = p2[i];
    float4 d = bb4[i % (GN / 4)];
    float4 r;
    r.x = a.x + b.x + c.x + d.x;
    r.y = a.y + b.y + c.y + d.y;
    r.z = a.z + b.z + c.z + d.z;
    r.w = a.w + b.w + c.w + d.w;
    ((float4*)out)[i] = r;
}

// ---------------------------------------------------------------------------
extern "C" void kernel_launch(void* const* d_in, const int* in_sizes, int n_in,
                              void* d_out, int out_size) {
    const float* wf  = (const float*)d_in[0];   // [4,8192,768] f32
    const int*   ids = (const int*)d_in[1];     // [4,8192] i32
    const float* W2  = (const float*)d_in[2];   // [768,768] f32
    const float* b2  = (const float*)d_in[3];   // [768] f32
    float* out = (float*)d_out;                 // [4,100,768] f32

    init_kernel<<<300, 1024>>>(ids);                       // 307200 threads
    transpose_kernel<<<dim3(24, 24), dim3(32, 8)>>>(W2);
    pool_kernel<<<dim3(LL / TCH, BB), PBLK>>>(wf, ids);
    gemm_kernel<<<dim3(GM / BMT, GN / BNT, SPLITK), GT>>>();
    combine_kernel<<<(GM * GN / 4 + 255) / 256, 256>>>(b2, out);
}

// round 4
// speedup vs baseline: 1.8949x; 1.1811x over previous
#include <cuda_runtime.h>
#include <math_constants.h>
#include <cstdint>

// Problem constants
#define BB 4
#define LL 8192
#define DD 768
#define MAXS 100
#define GM (BB*MAXS)   // 400
#define GN DD          // 768
#define GK DD          // 768

// pool config
#define TCH 32
#define PBLK 192

// gemm config
#define SPLITK 6
#define KCHUNK (GK/SPLITK)  // 128
#define KC 32
#define NITER (KCHUNK/KC)   // 4
#define BMT 100
#define BNT 32
#define GT 160

// setup kernel split
#define INIT_BLOCKS 1200                 // 307200 / 256
#define TRANS_BLOCKS (24*24)             // 576

// Scratch (device globals; allocation is forbidden)
__device__ float g_pooledT[GK][GM];          // [768][400]  A^T, k-major
__device__ float g_W2T[GK][GN];              // [768][768]  W2^T, k-major
__device__ float g_part[SPLITK][GM * GN];    // split-K partials

// ---------------------------------------------------------------------------
// helpers
// ---------------------------------------------------------------------------
__device__ __forceinline__ void atomMaxF(float* a, float v) {
    if (v >= 0.0f) atomicMax((int*)a, __float_as_int(v));
    else           atomicMin((unsigned int*)a, __float_as_uint(v));
}

__device__ __forceinline__ void cp_async16(unsigned int smem, const void* gmem) {
    asm volatile("cp.async.cg.shared.global [%0], [%1], 16;\n" :: "r"(smem), "l"(gmem));
}
__device__ __forceinline__ void cp_commit() {
    asm volatile("cp.async.commit_group;\n");
}
template <int N>
__device__ __forceinline__ void cp_wait() {
    asm volatile("cp.async.wait_group %0;\n" :: "n"(N));
}

// ---------------------------------------------------------------------------
// Setup: init pooledT (-inf on valid slots, 0 elsewhere)  +  transpose W2.
// Two independent jobs fused into one launch so they overlap.
// ---------------------------------------------------------------------------
__global__ __launch_bounds__(256) void setup_kernel(const int* __restrict__ ids,
                                                    const float* __restrict__ W2) {
    __shared__ float tile[32][33];
    if (blockIdx.x < INIT_BLOCKS) {
        int i = blockIdx.x * 256 + threadIdx.x;        // over GK*GM = 307200
        int m = i % GM;
        int b = m / MAXS;
        int s = m - b * MAXS;
        int bbmax = ids[b * LL + LL - 1];              // ids sorted -> max id
        ((float*)g_pooledT)[i] = (s < bbmax) ? -CUDART_INF_F : 0.0f;
    } else {
        int bid = blockIdx.x - INIT_BLOCKS;
        int bx = (bid % 24) * 32;   // k base
        int by = (bid / 24) * 32;   // n base
        int x = threadIdx.x & 31;
        int y = threadIdx.x >> 5;   // 0..7
#pragma unroll
        for (int j = 0; j < 32; j += 8)
            tile[y + j][x] = W2[(size_t)(by + y + j) * GK + bx + x];
        __syncthreads();
#pragma unroll
        for (int j = 0; j < 32; j += 8)
            g_W2T[bx + y + j][by + x] = tile[x][y + j];
    }
}

// ---------------------------------------------------------------------------
// Pool: token-parallel segment max. grid (L/TCH, B), 192 threads.
// Thread owns float4 column; 8 LDG.128 in flight; streaming loads (__ldcs).
// ids sorted -> flushes rare & warp-uniform; exact float atomics.
// ---------------------------------------------------------------------------
__global__ __launch_bounds__(PBLK) void pool_kernel(const float* __restrict__ wf,
                                                    const int* __restrict__ ids) {
    __shared__ int sid[TCH];
    const int b = blockIdx.y;
    const int c0 = blockIdx.x * TCH;
    const int tid = threadIdx.x;
    if (tid < TCH) sid[tid] = ids[b * LL + c0 + tid];
    __syncthreads();

    const float4* __restrict__ base =
        (const float4*)(wf + ((size_t)b * LL + c0) * DD) + tid;   // row stride DD/4

    float4 run = make_float4(-CUDART_INF_F, -CUDART_INF_F, -CUDART_INF_F, -CUDART_INF_F);
    int cur = -1;
    const int d0 = tid * 4;

#pragma unroll
    for (int t0 = 0; t0 < TCH; t0 += 8) {
        float4 v[8];
#pragma unroll
        for (int j = 0; j < 8; ++j)
            v[j] = __ldcs(base + (size_t)(t0 + j) * (DD / 4));
#pragma unroll
        for (int j = 0; j < 8; ++j) {
            int id = sid[t0 + j];
            if (id != cur) {
                if (cur > 0) {
                    int m = b * MAXS + cur - 1;
                    atomMaxF(&g_pooledT[d0 + 0][m], run.x);
                    atomMaxF(&g_pooledT[d0 + 1][m], run.y);
                    atomMaxF(&g_pooledT[d0 + 2][m], run.z);
                    atomMaxF(&g_pooledT[d0 + 3][m], run.w);
                }
                cur = id;
                run = make_float4(-CUDART_INF_F, -CUDART_INF_F, -CUDART_INF_F, -CUDART_INF_F);
            }
            if (id > 0) {
                run.x = fmaxf(run.x, v[j].x);
                run.y = fmaxf(run.y, v[j].y);
                run.z = fmaxf(run.z, v[j].z);
                run.w = fmaxf(run.w, v[j].w);
            }
        }
    }
    if (cur > 0) {
        int m = b * MAXS + cur - 1;
        atomMaxF(&g_pooledT[d0 + 0][m], run.x);
        atomMaxF(&g_pooledT[d0 + 1][m], run.y);
        atomMaxF(&g_pooledT[d0 + 2][m], run.z);
        atomMaxF(&g_pooledT[d0 + 3][m], run.w);
    }
}

// ---------------------------------------------------------------------------
// GEMM: part[kz][m][n] = sum_{k in chunk kz} AT[k][m] * W2T[k][n]
// grid (4, 24, 6) = 576 blocks (~4/SM). 160 threads = 5 warps, micro 5x4.
// cp.async double-buffered smem pipeline; no register staging.
// ---------------------------------------------------------------------------
__global__ __launch_bounds__(GT) void gemm_kernel() {
    __shared__ float As[2][KC * BMT];   // 12.8 KB each
    __shared__ float Bs[2][KC * BNT];   // 4.0 KB each

    const int mb = blockIdx.x * BMT;
    const int nb = blockIdx.y * BNT;
    const int kbase = blockIdx.z * KCHUNK;

    const int tid = threadIdx.x;
    const int tx = tid & 7;     // n micro (x4)
    const int ty = tid >> 3;    // m micro (x5)
    const int ty5 = ty * 5;
    const int tx4 = tx * 4;

    const unsigned int sA0 = (unsigned int)__cvta_generic_to_shared(&As[0][0]);
    const unsigned int sB0 = (unsigned int)__cvta_generic_to_shared(&Bs[0][0]);

    // issue cp.async loads for one KC-tile into buffer `buf`
    auto load_tile = [&](int buf, int kt) {
        const unsigned int sa = sA0 + (unsigned int)(buf * KC * BMT * 4);
        const unsigned int sb = sB0 + (unsigned int)(buf * KC * BNT * 4);
        // A: KC*BMT/4 = 800 float4, 5 per thread. mb is a multiple of 100 ->
        // byte offset mb*4 is 16B-aligned; rows are 25 float4.
#pragma unroll
        for (int j = 0; j < 5; ++j) {
            int i = tid + j * GT;           // 0..799
            int k = i / 25;
            int m4 = i - k * 25;
            cp_async16(sa + (unsigned int)((k * BMT + m4 * 4) * 4),
                       &g_pooledT[kbase + kt + k][mb + m4 * 4]);
        }
        // B: KC*BNT/4 = 256 float4, strided (1-2 per thread)
        for (int i = tid; i < KC * BNT / 4; i += GT) {
            int k = i >> 3;
            int n4 = i & 7;
            cp_async16(sb + (unsigned int)((k * BNT + n4 * 4) * 4),
                       &g_W2T[kbase + kt + k][nb + n4 * 4]);
        }
        cp_commit();
    };

    float acc[5][4];
#pragma unroll
    for (int i = 0; i < 5; ++i)
#pragma unroll
        for (int j = 0; j < 4; ++j) acc[i][j] = 0.0f;

    load_tile(0, 0);

    for (int it = 0; it < NITER; ++it) {
        cp_wait<0>();
        __syncthreads();                       // tile `it` visible to all

        if (it + 1 < NITER) load_tile((it + 1) & 1, (it + 1) * KC);

        const float* __restrict__ Ab = &As[it & 1][0];
        const float* __restrict__ Bb = &Bs[it & 1][0];
#pragma unroll
        for (int k = 0; k < KC; ++k) {
            float a0 = Ab[k * BMT + ty5 + 0];
            float a1 = Ab[k * BMT + ty5 + 1];
            float a2 = Ab[k * BMT + ty5 + 2];
            float a3 = Ab[k * BMT + ty5 + 3];
            float a4 = Ab[k * BMT + ty5 + 4];
            float4 b4 = *(const float4*)&Bb[k * BNT + tx4];
            acc[0][0] = fmaf(a0, b4.x, acc[0][0]); acc[0][1] = fmaf(a0, b4.y, acc[0][1]);
            acc[0][2] = fmaf(a0, b4.z, acc[0][2]); acc[0][3] = fmaf(a0, b4.w, acc[0][3]);
            acc[1][0] = fmaf(a1, b4.x, acc[1][0]); acc[1][1] = fmaf(a1, b4.y, acc[1][1]);
            acc[1][2] = fmaf(a1, b4.z, acc[1][2]); acc[1][3] = fmaf(a1, b4.w, acc[1][3]);
            acc[2][0] = fmaf(a2, b4.x, acc[2][0]); acc[2][1] = fmaf(a2, b4.y, acc[2][1]);
            acc[2][2] = fmaf(a2, b4.z, acc[2][2]); acc[2][3] = fmaf(a2, b4.w, acc[2][3]);
            acc[3][0] = fmaf(a3, b4.x, acc[3][0]); acc[3][1] = fmaf(a3, b4.y, acc[3][1]);
            acc[3][2] = fmaf(a3, b4.z, acc[3][2]); acc[3][3] = fmaf(a3, b4.w, acc[3][3]);
            acc[4][0] = fmaf(a4, b4.x, acc[4][0]); acc[4][1] = fmaf(a4, b4.y, acc[4][1]);
            acc[4][2] = fmaf(a4, b4.z, acc[4][2]); acc[4][3] = fmaf(a4, b4.w, acc[4][3]);
        }
        __syncthreads();                       // done reading buf before reuse
    }

    float* __restrict__ part = g_part[blockIdx.z];
#pragma unroll
    for (int i = 0; i < 5; ++i) {
        int m = mb + ty5 + i;
        float4 st = make_float4(acc[i][0], acc[i][1], acc[i][2], acc[i][3]);
        *(float4*)&part[(size_t)m * GN + nb + tx4] = st;
    }
}

// ---------------------------------------------------------------------------
// Combine split-K partials + bias (float4)
// ---------------------------------------------------------------------------
__global__ __launch_bounds__(256) void combine_kernel(const float* __restrict__ b2,
                                                      float* __restrict__ out) {
    int i = blockIdx.x * 256 + threadIdx.x;       // over GM*GN/4 = 76800
    float4 r = ((const float4*)b2)[i % (GN / 4)];
#pragma unroll
    for (int z = 0; z < SPLITK; ++z) {
        float4 p = ((const float4*)g_part[z])[i];
        r.x += p.x; r.y += p.y; r.z += p.z; r.w += p.w;
    }
    ((float4*)out)[i] = r;
}

// ---------------------------------------------------------------------------
extern "C" void kernel_launch(void* const* d_in, const int* in_sizes, int n_in,
                              void* d_out, int out_size) {
    const float* wf  = (const float*)d_in[0];   // [4,8192,768] f32
    const int*   ids = (const int*)d_in[1];     // [4,8192] i32
    const float* W2  = (const float*)d_in[2];   // [768,768] f32
    const float* b2  = (const float*)d_in[3];   // [768] f32
    float* out = (float*)d_out;                 // [4,100,768] f32

    setup_kernel<<<INIT_BLOCKS + TRANS_BLOCKS, 256>>>(ids, W2);
    pool_kernel<<<dim3(LL / TCH, BB), PBLK>>>(wf, ids);
    gemm_kernel<<<dim3(GM / BMT, GN / BNT, SPLITK), GT>>>();
    combine_kernel<<<(GM * GN / 4 + 255) / 256, 256>>>(b2, out);
}